// round 8
// baseline (speedup 1.0000x reference)
#include <cuda_runtime.h>

// Closed form of the whole circuit:
//   e_w = cos(theta_w) * prod_{k<=w} cos(x_k)  -  sin(theta_w) * sin(x_w) * sin(x_{w+1})
// with sin(x_4) := 1.
//
// Persistent double-buffered cp.async pipeline. Round 6 showed one-shot
// blocks run load-phase and compute-phase in lockstep (all blocks wait, then
// all compute): phases never overlap. Here each block walks tiles
// grid-stride, issuing tile t+stride's cp.async group BEFORE waiting on
// tile t, so the next tile's loads stream under the current tile's compute.

#define BLOCK 256
#define ELTS 4
#define TILE (BLOCK * ELTS)   // 1024 elements / tile
#define GRID 296              // 2 blocks per SM on 148 SMs

__device__ __forceinline__ void issue_tile(const float* __restrict__ x,
                                           unsigned smem_buf, int tile, int tid) {
#pragma unroll
    for (int e = 0; e < ELTS; e++) {
        int b = tile * TILE + e * BLOCK + tid;
        const float* gp = x + (long)b * 8;               // first 16B of row b
        unsigned sp = smem_buf + (e * BLOCK + tid) * 16;
        asm volatile("cp.async.cg.shared.global [%0], [%1], 16;"
                     :: "r"(sp), "l"(gp));
    }
}

__global__ void __launch_bounds__(BLOCK)
qlayer_kernel(const float* __restrict__ x, const float* __restrict__ w,
              float* __restrict__ out, int n) {
    __shared__ float4 sx[2][TILE];

    int tid = threadIdx.x;
    int ntiles = n / TILE;
    int stride = gridDim.x;

    unsigned sbase;
    asm("{ .reg .u64 t; cvta.to.shared.u64 t, %1; cvt.u32.u64 %0, t; }"
        : "=r"(sbase) : "l"(sx));

    // Prologue: first tile's loads in flight immediately.
    int t0 = blockIdx.x;
    if (t0 < ntiles) issue_tile(x, sbase, t0, tid);
    asm volatile("cp.async.commit_group;");

    // Weight trig (uniform) overlaps the prologue loads.
    float4 wv = *reinterpret_cast<const float4*>(w);
    float sw0, cw0, sw1, cw1, sw2, cw2, sw3, cw3;
    __sincosf(wv.x, &sw0, &cw0);
    __sincosf(wv.y, &sw1, &cw1);
    __sincosf(wv.z, &sw2, &cw2);
    __sincosf(wv.w, &sw3, &cw3);

    int buf = 0;
    for (int t = t0; t < ntiles; t += stride, buf ^= 1) {
        // Issue next tile before consuming this one.
        int tn = t + stride;
        if (tn < ntiles)
            issue_tile(x, sbase + (buf ^ 1) * (TILE * 16), tn, tid);
        asm volatile("cp.async.commit_group;");
        // Wait until only the just-committed group can be pending -> tile t ready.
        asm volatile("cp.async.wait_group 1;" ::: "memory");
        // Each thread reads only slots it wrote itself -> no __syncthreads.

#pragma unroll
        for (int e = 0; e < ELTS; e++) {
            int b = t * TILE + e * BLOCK + tid;
            float4 xv = sx[buf][e * BLOCK + tid];

            float s0, c0, s1, c1, s2, c2, s3, c3;
            __sincosf(xv.x, &s0, &c0);
            __sincosf(xv.y, &s1, &c1);
            __sincosf(xv.z, &s2, &c2);
            __sincosf(xv.w, &s3, &c3);

            float d0 = c0;
            float d1 = d0 * c1;
            float d2 = d1 * c2;
            float d3 = d2 * c3;

            float4 o;
            o.x = fmaf(cw0, d0, -sw0 * (s0 * s1));
            o.y = fmaf(cw1, d1, -sw1 * (s1 * s2));
            o.z = fmaf(cw2, d2, -sw2 * (s2 * s3));
            o.w = fmaf(cw3, d3, -sw3 * s3);
            reinterpret_cast<float4*>(out)[b] = o;
        }
    }

    // Ragged tail (empty for B = 1M).
    for (int b = ntiles * TILE + blockIdx.x * BLOCK + tid; b < n;
         b += stride * BLOCK) {
        float4 xv = reinterpret_cast<const float4*>(x)[(long)b * 2];
        float s0, c0, s1, c1, s2, c2, s3, c3;
        __sincosf(xv.x, &s0, &c0);
        __sincosf(xv.y, &s1, &c1);
        __sincosf(xv.z, &s2, &c2);
        __sincosf(xv.w, &s3, &c3);

        float d0 = c0;
        float d1 = d0 * c1;
        float d2 = d1 * c2;
        float d3 = d2 * c3;

        float4 o;
        o.x = fmaf(cw0, d0, -sw0 * (s0 * s1));
        o.y = fmaf(cw1, d1, -sw1 * (s1 * s2));
        o.z = fmaf(cw2, d2, -sw2 * (s2 * s3));
        o.w = fmaf(cw3, d3, -sw3 * s3);
        reinterpret_cast<float4*>(out)[b] = o;
    }
}

extern "C" void kernel_launch(void* const* d_in, const int* in_sizes, int n_in,
                              void* d_out, int out_size) {
    const float* x = (const float*)d_in[0];        // [B, 8]
    const float* weights = (const float*)d_in[1];  // [4]
    float* out = (float*)d_out;                    // [B, 4]
    int n = in_sizes[0] / 8;

    int blocks = GRID;
    int max_tiles = n / TILE;
    if (max_tiles > 0 && max_tiles < blocks) blocks = max_tiles;
    if (blocks < 1) blocks = 1;
    qlayer_kernel<<<blocks, BLOCK>>>(x, weights, out, n);
}